// round 16
// speedup vs baseline: 14.2754x; 1.0586x over previous
#include <cuda_runtime.h>
#include <math.h>
#include <stdint.h>

// ---------------- problem constants ----------------
#define BB 2
#define TT 1024
#define CC 1024
#define HH 16
#define VD 32
#define NOPE_ 32
#define RP 32
#define RD 64
#define DQK 96
#define KEEP_ 256
#define QL 96
#define KVL 32

#define LOG1E4_OVER_32 0.28782313662425572f   // ln(10000)/32
#define ATTN_SCALE 0.10206207261596577f       // 1/sqrt(96)

// ---------------- rounded-weight region offsets ----------------
constexpr int WTF_WINK = 0;
constexpr int WTF_WINV = WTF_WINK + 1024*1536;
constexpr int WTF_SELK = WTF_WINV + 1024*512;
constexpr int WTF_SELV = WTF_SELK + 1024*1536;
constexpr int WTF_PROJ = WTF_SELV + 1024*512;
constexpr int WTF_DQN  = WTF_PROJ + 512*1024;
constexpr int WTF_DQR  = WTF_DQN  + 96*512;
constexpr int WTF_DKN  = WTF_DQR  + 96*1024;
constexpr int WTF_DV   = WTF_DKN  + 32*512;
constexpr int WTF_TOTAL = WTF_DV + 32*512;
constexpr int WTF_BLOCKS = WTF_TOTAL / 1024;   // 4784

// ---------------- scratch ----------------
constexpr int OFF_WC1     = 0;
constexpr int OFF_WTF     = OFF_WC1     + 1024*256;
constexpr int OFF_XTF     = OFF_WTF     + WTF_TOTAL;
constexpr int OFF_F0      = OFF_XTF     + 2048*1024;
constexpr int OFF_QOUT    = OFF_F0      + 2048*256;
constexpr int OFF_KVOUT   = OFF_QOUT    + 2048*1536;
constexpr int OFF_WINOUT  = OFF_KVOUT   + 2048*1024;
constexpr int OFF_SELKV   = OFF_WINOUT  + 2048*2048;
constexpr int OFF_XMEAN   = OFF_SELKV   + 512*2048;
constexpr int OFF_GATE    = OFF_XMEAN   + BB*CC;
constexpr int OFF_SCORES  = OFF_GATE    + 8;
constexpr int OFF_IDX     = OFF_SCORES  + BB*TT;
constexpr int OFF_Q       = OFF_IDX     + BB*KEEP_;
constexpr int OFF_K1      = OFF_Q       + BB*HH*TT*DQK;
constexpr int OFF_KW      = OFF_K1      + BB*HH*TT*DQK;
constexpr int OFF_KS      = OFF_KW      + BB*HH*TT*DQK;
constexpr int OFF_ATTN    = OFF_KS      + BB*HH*KEEP_*DQK;
constexpr int OFF_ATTN2   = OFF_ATTN    + BB*TT*HH*VD;
constexpr int OFF_ATTN3   = OFF_ATTN2   + BB*TT*HH*VD;
constexpr int SCRATCH_TOTAL = OFF_ATTN3 + BB*TT*HH*VD;

__device__ __align__(256) float g_scratch[SCRATCH_TOTAL];

// ---------------- tf32 helpers ----------------
__device__ __forceinline__ float to_tf32(float v) {
    uint32_t u;
    asm("cvt.rna.tf32.f32 %0, %1;" : "=r"(u) : "f"(v));
    return __uint_as_float(u);
}

__device__ __forceinline__ void mma_tf32(float* d, const uint32_t* a, const uint32_t* b) {
    asm volatile(
        "mma.sync.aligned.m16n8k8.row.col.f32.tf32.tf32.f32 "
        "{%0,%1,%2,%3}, {%4,%5,%6,%7}, {%8,%9}, {%0,%1,%2,%3};\n"
        : "+f"(d[0]), "+f"(d[1]), "+f"(d[2]), "+f"(d[3])
        : "r"(a[0]), "r"(a[1]), "r"(a[2]), "r"(a[3]), "r"(b[0]), "r"(b[1]));
}

// ldmatrix x4 on fp32 data (CUTLASS tf32 trick): lane L gets element (row L/4, col L%4)
// of each 8x4-float tile; tiles from address lanes 0-7 / 8-15 / 16-23 / 24-31.
__device__ __forceinline__ void ldsm_x4(uint32_t* r, uint32_t addr) {
    asm volatile("ldmatrix.sync.aligned.m8n8.x4.shared.b16 {%0,%1,%2,%3}, [%4];"
                 : "=r"(r[0]), "=r"(r[1]), "=r"(r[2]), "=r"(r[3]) : "r"(addr));
}

__device__ __forceinline__ void cp16(uint32_t dst, const float* src) {
    asm volatile("cp.async.cg.shared.global [%0], [%1], 16;" :: "r"(dst), "l"(src));
}
#define CP_COMMIT() asm volatile("cp.async.commit_group;")

// ---------------- multi-GEMM job table ----------------
struct GemmJob {
    const float* A; int lda;
    const float* B0; int ldb0; int n0;
    const float* B1; int ldb1;
    float* C; int ldc;
    int K;
    int ctaStart;
    int nx;
    const int* rowIdx;
    int rnd;
};
struct GemmJobs { GemmJob j[3]; };

constexpr int G2_A = 128 * 20;
constexpr int G2_B = 16 * 136;
constexpr int G2_SMEM = 3 * (G2_A + G2_B) * 4;   // 56832 B

__global__ void __launch_bounds__(256, 2)
gemm_multi(GemmJobs jobs, int njobs) {
    extern __shared__ float sm2[];
    float* As = sm2;
    float* Bs = sm2 + 3 * G2_A;

    int linear = blockIdx.x;
    int ji = njobs - 1;
#pragma unroll
    for (int t = 1; t < 3; t++)
        if (t < njobs && linear < jobs.j[t].ctaStart) { ji = t - 1; break; }
    const GemmJob& J = jobs.j[ji];
    int local = linear - J.ctaStart;
    int bx = local % J.nx, by = local / J.nx;

    const float* A = J.A; int lda = J.lda;
    float* C = J.C; int ldc = J.ldc;
    int K = J.K;
    int row0 = by * 128, col0 = bx * 128;

    const float* Bsrc;
    int ldb;
    if (col0 < J.n0) { Bsrc = J.B0 + col0; ldb = J.ldb0; }
    else             { Bsrc = J.B1 + (col0 - J.n0); ldb = J.ldb1; }

    int tid = threadIdx.x;
    int warp = tid >> 5, lane = tid & 31;
    int g = lane >> 2, tg = lane & 3;
    int wm = warp >> 2, wn = warp & 3;

    uint32_t as_addr = (uint32_t)__cvta_generic_to_shared(As);
    uint32_t bs_addr = (uint32_t)__cvta_generic_to_shared(Bs);

    int ar0 = row0 + (tid >> 2);
    int ar1 = row0 + 64 + (tid >> 2);
    if (J.rowIdx) { ar0 = J.rowIdx[ar0]; ar1 = J.rowIdx[ar1]; }
    const float* Ag0 = A + (size_t)ar0 * lda + (tid & 3) * 4;
    const float* Ag1 = A + (size_t)ar1 * lda + (tid & 3) * 4;
    const float* Bg0 = Bsrc + (size_t)(tid >> 5) * ldb + (tid & 31) * 4;
    const float* Bg1 = Bsrc + (size_t)(8 + (tid >> 5)) * ldb + (tid & 31) * 4;
    uint32_t offA0 = (((tid >> 2)) * 20 + (tid & 3) * 4) * 4;
    uint32_t offA1 = (((tid >> 2) + 64) * 20 + (tid & 3) * 4) * 4;
    uint32_t offB0 = ((tid >> 5) * 136 + (tid & 31) * 4) * 4;
    uint32_t offB1 = ((8 + (tid >> 5)) * 136 + (tid & 31) * 4) * 4;

    // ldmatrix per-thread A offset: rows wm*64 + rowoff (+mi*16), k = koff (+ks)
    int rowoff = (lane & 7) + ((lane & 8) ? 8 : 0);
    int koffA  = (lane & 16) ? 4 : 0;
    uint32_t lmA = (uint32_t)(((wm * 64 + rowoff) * 20 + koffA) * 4);

    float d[4][4][4];
#pragma unroll
    for (int mi = 0; mi < 4; mi++)
#pragma unroll
        for (int ni = 0; ni < 4; ni++)
#pragma unroll
            for (int r = 0; r < 4; r++) d[mi][ni][r] = 0.f;

    int nk = K / 16;

    {
        cp16(as_addr + offA0, Ag0);
        cp16(as_addr + offA1, Ag1);
        cp16(bs_addr + offB0, Bg0);
        cp16(bs_addr + offB1, Bg1);
        CP_COMMIT();
    }
    if (nk > 1) {
        uint32_t ab = as_addr + G2_A * 4, bb = bs_addr + G2_B * 4;
        cp16(ab + offA0, Ag0 + 16);
        cp16(ab + offA1, Ag1 + 16);
        cp16(bb + offB0, Bg0 + (size_t)16 * ldb);
        cp16(bb + offB1, Bg1 + (size_t)16 * ldb);
        CP_COMMIT();
    }

    for (int kt = 0; kt < nk; kt++) {
        if (kt + 1 < nk) { asm volatile("cp.async.wait_group 1;"); }
        else             { asm volatile("cp.async.wait_group 0;"); }
        __syncthreads();

        if (kt + 2 < nk) {
            int s = (kt + 2) % 3;
            int k0 = (kt + 2) * 16;
            uint32_t ab = as_addr + s * G2_A * 4, bb = bs_addr + s * G2_B * 4;
            cp16(ab + offA0, Ag0 + k0);
            cp16(ab + offA1, Ag1 + k0);
            cp16(bb + offB0, Bg0 + (size_t)k0 * ldb);
            cp16(bb + offB1, Bg1 + (size_t)k0 * ldb);
            CP_COMMIT();
        }

        const float* Bc = Bs + (kt % 3) * G2_B;
        uint32_t abase = as_addr + (kt % 3) * G2_A * 4 + lmA;

#pragma unroll
        for (int ks = 0; ks < 16; ks += 8) {
            uint32_t bf[4][2];
#pragma unroll
            for (int ni = 0; ni < 4; ni++) {
                int c = wn * 32 + ni * 8 + g;
                bf[ni][0] = __float_as_uint(Bc[(ks + tg) * 136 + c]);
                bf[ni][1] = __float_as_uint(Bc[(ks + tg + 4) * 136 + c]);
            }
#pragma unroll
            for (int mi = 0; mi < 4; mi++) {
                uint32_t af[4];
                ldsm_x4(af, abase + (uint32_t)((mi * 320 + ks) * 4));
#pragma unroll
                for (int ni = 0; ni < 4; ni++) {
                    mma_tf32(d[mi][ni], af, bf[ni]);
                }
            }
        }
    }

    if (J.rnd) {
#pragma unroll
        for (int mi = 0; mi < 4; mi++)
#pragma unroll
            for (int ni = 0; ni < 4; ni++)
#pragma unroll
                for (int r = 0; r < 4; r++) d[mi][ni][r] = to_tf32(d[mi][ni][r]);
    }
#pragma unroll
    for (int mi = 0; mi < 4; mi++) {
#pragma unroll
        for (int ni = 0; ni < 4; ni++) {
            int r = row0 + wm * 64 + mi * 16 + g;
            int c = col0 + wn * 32 + ni * 8 + 2 * tg;
            *(float2*)(C + (size_t)r * ldc + c) = make_float2(d[mi][ni][0], d[mi][ni][1]);
            *(float2*)(C + (size_t)(r + 8) * ldc + c) = make_float2(d[mi][ni][2], d[mi][ni][3]);
        }
    }
}

// ---------------- fused prep ----------------
__global__ void prep_kernel(const float* __restrict__ x, const float* __restrict__ w_imp,
                            float* __restrict__ scores, float* __restrict__ xtf,
                            float* __restrict__ xmean,
                            const float* __restrict__ w_cq, const float* __restrict__ w_ckv,
                            const float* __restrict__ w_krope, float* __restrict__ wc1,
                            const float* __restrict__ w_wink, const float* __restrict__ w_winv,
                            const float* __restrict__ w_selk, const float* __restrict__ w_selv,
                            const float* __restrict__ w_proj,
                            const float* __restrict__ w_dqn, const float* __restrict__ w_dqr,
                            const float* __restrict__ w_dkn, const float* __restrict__ w_dv,
                            float* __restrict__ wtf) {
    int blk = blockIdx.x, tid = threadIdx.x;
    if (blk < 2048) {
        __shared__ float s8[8];
        int row = blk;
        float s = 0.f;
        for (int c = tid; c < CC; c += 256) {
            float xv = x[row * CC + c];
            xtf[row * CC + c] = to_tf32(xv);
            s += xv * w_imp[c];
        }
#pragma unroll
        for (int o = 16; o > 0; o >>= 1) s += __shfl_xor_sync(0xffffffffu, s, o);
        if ((tid & 31) == 0) s8[tid >> 5] = s;
        __syncthreads();
        if (tid == 0) {
            float t = 0.f;
#pragma unroll
            for (int i = 0; i < 8; i++) t += s8[i];
            scores[row] = t;
        }
    } else if (blk < 2056) {
        int i = blk - 2048;
        int b = i >> 2;
        int c = (i & 3) * 256 + tid;
        float s = 0.f;
        for (int t = 0; t < TT; t++) s += x[(b * TT + t) * CC + c];
        xmean[b * CC + c] = s * (1.f / (float)TT);
    } else if (blk < 3080) {
        int k = blk - 2056;
        float v;
        if (tid < 96) v = w_cq[k * 96 + tid];
        else if (tid < 128) v = w_ckv[k * 32 + (tid - 96)];
        else if (tid < 192) v = w_krope[k * 64 + (tid - 128)];
        else v = 0.f;
        wc1[k * 256 + tid] = to_tf32(v);
    } else {
        int off = (blk - 3080) * 1024 + tid * 4;
        const float* src;
        int rel;
        if (off < WTF_WINV)      { src = w_wink; rel = off - WTF_WINK; }
        else if (off < WTF_SELK) { src = w_winv; rel = off - WTF_WINV; }
        else if (off < WTF_SELV) { src = w_selk; rel = off - WTF_SELK; }
        else if (off < WTF_PROJ) { src = w_selv; rel = off - WTF_SELV; }
        else if (off < WTF_DQN)  { src = w_proj; rel = off - WTF_PROJ; }
        else if (off < WTF_DQR)  { src = w_dqn;  rel = off - WTF_DQN; }
        else if (off < WTF_DKN)  { src = w_dqr;  rel = off - WTF_DQR; }
        else if (off < WTF_DV)   { src = w_dkn;  rel = off - WTF_DKN; }
        else                     { src = w_dv;   rel = off - WTF_DV; }
        float4 v = *(const float4*)(src + rel);
        v.x = to_tf32(v.x); v.y = to_tf32(v.y);
        v.z = to_tf32(v.z); v.w = to_tf32(v.w);
        *(float4*)(wtf + off) = v;
    }
}

// ---------------- fused topk + gate ----------------
__global__ void topk_gate_kernel(const float* __restrict__ scores, int* __restrict__ idxout,
                                 const float* __restrict__ xmean, const float* __restrict__ wg,
                                 float* __restrict__ gate) {
    int blk = blockIdx.x, tid = threadIdx.x;
    if (blk < 2) {
        __shared__ float sv[1024];
        __shared__ int si[1024];
        __shared__ int ti[256];
        int b = blk;
        sv[tid] = scores[b * TT + tid];
        si[tid] = tid;
        __syncthreads();
        for (int k = 2; k <= 1024; k <<= 1) {
            for (int j = k >> 1; j > 0; j >>= 1) {
                int ixj = tid ^ j;
                if (ixj > tid) {
                    bool desc = ((tid & k) == 0);
                    float va = sv[tid], vb = sv[ixj];
                    int ia = si[tid], ib = si[ixj];
                    bool agtb = (va > vb) || (va == vb && ia < ib);
                    if (desc ? !agtb : agtb) {
                        sv[tid] = vb; sv[ixj] = va;
                        si[tid] = ib; si[ixj] = ia;
                    }
                }
                __syncthreads();
            }
        }
        if (tid < 256) ti[tid] = si[tid];
        __syncthreads();
        for (int k = 2; k <= 256; k <<= 1) {
            for (int j = k >> 1; j > 0; j >>= 1) {
                int ixj = tid ^ j;
                if (tid < 256 && ixj > tid) {
                    bool asc = ((tid & k) == 0);
                    int ia = ti[tid], ib = ti[ixj];
                    if (asc ? (ia > ib) : (ia < ib)) { ti[tid] = ib; ti[ixj] = ia; }
                }
                __syncthreads();
            }
        }
        if (tid < 256) idxout[b * KEEP_ + tid] = b * TT + ti[tid];
    } else {
        int b = blk - 2;
        __shared__ float sg[3];
        int w = tid >> 5, lane = tid & 31;
        if (w < 3) {
            float s = 0.f;
            for (int c = lane; c < CC; c += 32) s += xmean[b * CC + c] * wg[c * 3 + w];
#pragma unroll
            for (int o = 16; o > 0; o >>= 1) s += __shfl_xor_sync(0xffffffffu, s, o);
            if (lane == 0) sg[w] = s;
        }
        __syncthreads();
        if (tid == 0) {
            float m = fmaxf(sg[0], fmaxf(sg[1], sg[2]));
            float e0 = expf(sg[0] - m), e1 = expf(sg[1] - m), e2 = expf(sg[2] - m);
            float inv = 1.f / (e0 + e1 + e2);
            gate[b * 4 + 0] = e0 * inv;
            gate[b * 4 + 1] = e1 * inv;
            gate[b * 4 + 2] = e2 * inv;
        }
    }
}

// ---------------- RMS norm on f0 ----------------
__global__ void rms2_kernel(float* __restrict__ f0,
                            const float* __restrict__ gq, const float* __restrict__ gkv) {
    int row = blockIdx.x, tid = threadIdx.x;
    float* dd = f0 + row * 256;
    __shared__ float s4[4];
    float v = (tid < 96) ? dd[tid] : 0.f;
    float sq = v * v;
#pragma unroll
    for (int o = 16; o > 0; o >>= 1) sq += __shfl_xor_sync(0xffffffffu, sq, o);
    if ((tid & 31) == 0) s4[tid >> 5] = sq;
    __syncthreads();
    float tot = s4[0] + s4[1] + s4[2] + s4[3];
    float sc = rsqrtf(tot / 96.f + 1e-6f);
    if (tid < 96) dd[tid] = to_tf32(v * sc * gq[tid]);
    __syncthreads();
    if (tid < 32) {
        float v2 = dd[96 + tid];
        float sq2 = v2 * v2;
#pragma unroll
        for (int o = 16; o > 0; o >>= 1) sq2 += __shfl_xor_sync(0xffffffffu, sq2, o);
        float sc2 = rsqrtf(sq2 / 32.f + 1e-6f);
        dd[96 + tid] = to_tf32(v2 * sc2 * gkv[tid]);
    }
}

// ---------------- fused assembles: Q + K only ----------------
__global__ void assemble_all_kernel(const float* __restrict__ qout,
                                    const float* __restrict__ kvout,
                                    const float* __restrict__ f0,
                                    const float* __restrict__ selkv,
                                    const float* __restrict__ winout,
                                    float* __restrict__ Q,
                                    float* __restrict__ K1,
                                    float* __restrict__ KSb,
                                    float* __restrict__ KWb) {
    int blk = blockIdx.x;
    int j = threadIdx.x;
    int h = j >> 5, d = j & 31;
    float f = expf(-LOG1E4_OVER_32 * (float)d);

    if (blk < 2048) {
        int row = blk;
        int b = row >> 10, t = row & 1023;
        int qb = (((b * HH + h) * TT) + t) * DQK;
        Q[qb + d] = qout[row * 1536 + j];
        float x1 = qout[row * 1536 + 512 + h * RD + d];
        float x2 = qout[row * 1536 + 512 + h * RD + RP + d];
        float sn, cs;
        sincosf((float)t * f, &sn, &cs);
        Q[qb + NOPE_ + d] = to_tf32(x1 * cs - x2 * sn);
        Q[qb + NOPE_ + RP + d] = to_tf32(x1 * sn + x2 * cs);
    } else if (blk < 4096) {
        int row = blk - 2048;
        int b = row >> 10, t = row & 1023;
        int kb = (((b * HH + h) * TT) + t) * DQK;
        K1[kb + d] = kvout[row * 1024 + j];
        float x1 = f0[row * 256 + 128 + d] * 0.0625f;
        float x2 = f0[row * 256 + 128 + RP + d] * 0.0625f;
        float sn, cs;
        sincosf((float)t * f, &sn, &cs);
        K1[kb + NOPE_ + d] = to_tf32(x1 * cs - x2 * sn);
        K1[kb + NOPE_ + RP + d] = to_tf32(x1 * sn + x2 * cs);
    } else {
        const float* raw;
        float* K;
        int row, S;
        if (blk < 4608) { row = blk - 4096; S = KEEP_; raw = selkv; K = KSb; }
        else            { row = blk - 4608; S = TT;    raw = winout; K = KWb; }
        int b = row / S, pos = row % S;
        size_t base = (size_t)row * 2048;
        float nope = raw[base + h * DQK + d];
        float x1 = raw[base + h * DQK + NOPE_ + d];
        float x2 = raw[base + h * DQK + NOPE_ + RP + d];
        float sn, cs;
        sincosf((float)pos * f, &sn, &cs);
        int kb = (((b * HH + h) * S) + pos) * DQK;
        K[kb + d] = nope;
        K[kb + NOPE_ + d] = to_tf32(x1 * cs - x2 * sn);
        K[kb + NOPE_ + RP + d] = to_tf32(x1 * sn + x2 * cs);
    }
}

// ---------------- add att0+att1+att2 (rounded for proj A-side) ----------------
__global__ void attadd3_kernel(float* __restrict__ a0, const float* __restrict__ a1,
                               const float* __restrict__ a2) {
    int i = (blockIdx.x * 256 + threadIdx.x) * 4;
    float4 v0 = *(float4*)(a0 + i);
    float4 v1 = *(const float4*)(a1 + i);
    float4 v2 = *(const float4*)(a2 + i);
    v0.x = to_tf32(v0.x + v1.x + v2.x);
    v0.y = to_tf32(v0.y + v1.y + v2.y);
    v0.z = to_tf32(v0.z + v1.z + v2.z);
    v0.w = to_tf32(v0.w + v1.w + v2.w);
    *(float4*)(a0 + i) = v0;
}

// ---------------- pipelined tf32 MMA flash attention, 3-way split, 2 CTA/SM ----------
constexpr int QS_STR = 100;
constexpr int KS_STR = 100;
constexpr int VS_STR = 40;
constexpr int PS_STR = 68;
constexpr int KBUF = 64 * KS_STR;
constexpr int VBUF = 64 * VS_STR;
constexpr int ASM_KS = 0;                    // overlays Qs (dead after reg preload)
constexpr int ASM_VS = 2 * KBUF;
constexpr int ASM_PS = ASM_VS + 2 * VBUF;
constexpr int ATTN_SMEM = (ASM_PS + 8 * 16 * PS_STR) * 4;   // 106496 B

__global__ void __launch_bounds__(256, 2)
attn_mma(const float* __restrict__ Q,
         const float* __restrict__ K1, const float* __restrict__ KS,
         const float* __restrict__ KW,
         const float* __restrict__ kvout, const float* __restrict__ selkv,
         const float* __restrict__ winout,
         const float* __restrict__ gate,
         float* __restrict__ att0, float* __restrict__ att1, float* __restrict__ att2) {
    extern __shared__ float sm[];
    float* Qs = sm;

    int tid = threadIdx.x;
    int w = tid >> 5, lane = tid & 31;
    int g = lane >> 2, tg = lane & 3;
    float* Ps = sm + ASM_PS + w * 16 * PS_STR;

    int xid = blockIdx.x;
    int part = xid % 3;
    int tile = 7 - (xid / 3);
    int h = blockIdx.y, b = blockIdx.z;
    int q0 = tile * 128;
    int bh = b * HH + h;
    int rowg = q0 + 16 * w + g;

    int br = (part == 0) ? 0 : ((part == 1) ? 2 : 1);
    float* outp = (part == 0) ? att0 : ((part == 1) ? att1 : att2);
    bool causal = (br != 1);
    int nchunk = (br == 1) ? 4 : 2 * (tile + 1);

    const float* Kp = (br == 0) ? K1 + bh * TT * DQK
                    : (br == 1) ? KS + bh * KEEP_ * DQK
                                : KW + bh * TT * DQK;
    const float* Vp;
    int vld;
    if (br == 0)      { Vp = kvout + (size_t)(b * TT) * 1024 + 512 + h * VD;    vld = 1024; }
    else if (br == 1) { Vp = selkv + (size_t)(b * KEEP_) * 2048 + 1536 + h * VD; vld = 2048; }
    else              { Vp = winout + (size_t)(b * TT) * 2048 + 1536 + h * VD;   vld = 2048; }

    uint32_t smem_u32 = (uint32_t)__cvta_generic_to_shared(sm);

    // ---- phase 1: stage Q, preload register fragments, release smem ----
    const float* Qp = Q + (bh * TT + q0) * DQK;
    for (int i = tid; i < 128 * 24; i += 256) {
        int q = i / 24, dq = i % 24;
        float4 v = *(const float4*)(Qp + q * DQK + dq * 4);
        *(float4*)&Qs[q * QS_STR + dq * 4] = v;
    }
    __syncthreads();
    uint32_t Qf[12][4];
    {
        const float* q0p = &Qs[(16 * w + g) * QS_STR];
        const float* q1p = q0p + 8 * QS_STR;
#pragma unroll
        for (int ks = 0; ks < 12; ks++) {
            Qf[ks][0] = __float_as_uint(q0p[8 * ks + tg]);
            Qf[ks][1] = __float_as_uint(q1p[8 * ks + tg]);
            Qf[ks][2] = __float_as_uint(q0p[8 * ks + tg + 4]);
            Qf[ks][3] = __float_as_uint(q1p[8 * ks + tg + 4]);
        }
    }
    __syncthreads();

    // ---- ldmatrix per-thread offsets ----
    // K B-fragments: tiles (ni rows @kb), (ni rows @kb+4), (ni+1 rows @kb), (ni+1 @kb+4)
    uint32_t lmB = (uint32_t)(((((lane & 16) ? 8 : 0) + (lane & 7)) * KS_STR
                              + ((lane & 8) ? 4 : 0)) * 4);
    // Ps A-fragments: rows g / g+8, k offsets 0/4
    uint32_t lmP = (uint32_t)((((lane & 7) + ((lane & 8) ? 8 : 0)) * PS_STR
                              + ((lane & 16) ? 4 : 0)) * 4);
    uint32_t ps_u32 = smem_u32 + (ASM_PS + w * 16 * PS_STR) * 4 + lmP;

    auto stage = [&](int buf, int k0) {
        uint32_t kaddr = smem_u32 + (ASM_KS + buf * KBUF) * 4;
        uint32_t vaddr = smem_u32 + (ASM_VS + buf * VBUF) * 4;
#pragma unroll
        for (int it = 0; it < 6; it++) {
            int i = tid + it * 256;
            int key = i / 24, dq = i % 24;
            cp16(kaddr + (key * KS_STR + dq * 4) * 4, Kp + (k0 + key) * DQK + dq * 4);
        }
#pragma unroll
        for (int it = 0; it < 2; it++) {
            int i = tid + it * 256;
            int key = i >> 3, dq = i & 7;
            cp16(vaddr + (key * VS_STR + dq * 4) * 4, Vp + (size_t)(k0 + key) * vld + dq * 4);
        }
        CP_COMMIT();
    };

    stage(0, 0);
    int buf = 0;

    float m0 = -1e30f, m1 = -1e30f, l0 = 0.f, l1 = 0.f;
    float acc[4][4];
#pragma unroll
    for (int nv = 0; nv < 4; nv++)
#pragma unroll
        for (int r = 0; r < 4; r++) acc[nv][r] = 0.f;

    for (int c = 0; c < nchunk; c++) {
        int k0 = c * 64;

        // single sync per chunk: my stage(c) done; barrier proves all warps
        // finished chunk c-1 (so buf^1 is free) and all stage(c) data is visible.
        asm volatile("cp.async.wait_group 0;");
        __syncthreads();
        if (c + 1 < nchunk) stage(buf ^ 1, (c + 1) * 64);

        const float* Vc = sm + ASM_VS + buf * VBUF;
        uint32_t kc_u32 = smem_u32 + (ASM_KS + buf * KBUF) * 4 + lmB;

        float s[8][4];
#pragma unroll
        for (int ni = 0; ni < 8; ni++)
#pragma unroll
            for (int r = 0; r < 4; r++) s[ni][r] = 0.f;

#pragma unroll
        for (int ks = 0; ks < 12; ks++) {
            int kb = ks * 8;
#pragma unroll
            for (int ni = 0; ni < 8; ni += 2) {
                uint32_t bf4[4];
                ldsm_x4(bf4, kc_u32 + (uint32_t)((ni * 8 * KS_STR + kb) * 4));
                mma_tf32(s[ni], Qf[ks], &bf4[0]);
                mma_tf32(s[ni + 1], Qf[ks], &bf4[2]);
            }
        }

        if (causal && (k0 + 64 > q0)) {
#pragma unroll
            for (int ni = 0; ni < 8; ni++) {
                int key = k0 + 8 * ni + 2 * tg;
                if (key > rowg)         s[ni][0] = -1e30f;
                if (key + 1 > rowg)     s[ni][1] = -1e30f;
                if (key > rowg + 8)     s[ni][2] = -1e30f;
                if (key + 1 > rowg + 8) s[ni][3] = -1e30f;
            }
        }

        float cm0 = -1e30f, cm1 = -1e30f;
#pragma unroll
        for (int ni = 0; ni < 8; ni++) {
            cm0 = fmaxf(cm0, fmaxf(s[ni][0], s[ni][1]));
            cm1 = fmaxf(cm1, fmaxf(s[ni][2], s[ni][3]));
        }
        cm0 = fmaxf(cm0, __shfl_xor_sync(0xffffffffu, cm0, 1));
        cm0 = fmaxf(cm0, __shfl_xor_sync(0xffffffffu, cm0, 2));
        cm1 = fmaxf(cm1, __shfl_xor_sync(0xffffffffu, cm1, 1));
        cm1 = fmaxf(cm1, __shfl_xor_sync(0xffffffffu, cm1, 2));

        float nm0 = fmaxf(m0, cm0), nm1 = fmaxf(m1, cm1);
        float al0 = __expf((m0 - nm0) * ATTN_SCALE);
        float al1 = __expf((m1 - nm1) * ATTN_SCALE);
        m0 = nm0; m1 = nm1;

        float sum0 = 0.f, sum1 = 0.f;
#pragma unroll
        for (int ni = 0; ni < 8; ni++) {
            s[ni][0] = __expf((s[ni][0] - m0) * ATTN_SCALE);
            s[ni][1] = __expf((s[ni][1] - m0) * ATTN_SCALE);
            s[ni][2] = __expf((s[ni][2] - m1) * ATTN_SCALE);
            s[ni][3] = __expf((s[ni][3] - m1) * ATTN_SCALE);
            sum0 += s[ni][0] + s[ni][1];
            sum1 += s[ni][2] + s[ni][3];
        }
        sum0 += __shfl_xor_sync(0xffffffffu, sum0, 1);
        sum0 += __shfl_xor_sync(0xffffffffu, sum0, 2);
        sum1 += __shfl_xor_sync(0xffffffffu, sum1, 1);
        sum1 += __shfl_xor_sync(0xffffffffu, sum1, 2);
        l0 = l0 * al0 + sum0;
        l1 = l1 * al1 + sum1;

#pragma unroll
        for (int nv = 0; nv < 4; nv++) {
            acc[nv][0] *= al0; acc[nv][1] *= al0;
            acc[nv][2] *= al1; acc[nv][3] *= al1;
        }

        __syncwarp();
#pragma unroll
        for (int ni = 0; ni < 8; ni++) {
            *(float2*)&Ps[g * PS_STR + 8 * ni + 2 * tg] =
                make_float2(to_tf32(s[ni][0]), to_tf32(s[ni][1]));
            *(float2*)&Ps[(g + 8) * PS_STR + 8 * ni + 2 * tg] =
                make_float2(to_tf32(s[ni][2]), to_tf32(s[ni][3]));
        }
        __syncwarp();

#pragma unroll
        for (int ks = 0; ks < 8; ks++) {
            int kb = ks * 8;
            uint32_t Af[4];
            ldsm_x4(Af, ps_u32 + (uint32_t)(kb * 4));
#pragma unroll
            for (int nv = 0; nv < 4; nv++) {
                uint32_t Bf[2];
                Bf[0] = __float_as_uint(Vc[(kb + tg) * VS_STR + 8 * nv + g]);
                Bf[1] = __float_as_uint(Vc[(kb + tg + 4) * VS_STR + 8 * nv + g]);
                mma_tf32(acc[nv], Af, Bf);
            }
        }
        buf ^= 1;
    }

    float gb = gate[b * 4 + br];
    float inv0 = gb / l0, inv1 = gb / l1;
#pragma unroll
    for (int nv = 0; nv < 4; nv++) {
        int col = h * VD + 8 * nv + 2 * tg;
        *(float2*)(outp + (b * TT + rowg) * (HH * VD) + col) =
            make_float2(acc[nv][0] * inv0, acc[nv][1] * inv0);
        *(float2*)(outp + (b * TT + rowg + 8) * (HH * VD) + col) =
            make_float2(acc[nv][2] * inv1, acc[nv][3] * inv1);
    }
}

// ---------------- launcher ----------------
extern "C" void kernel_launch(void* const* d_in, const int* in_sizes, int n_in,
                              void* d_out, int out_size) {
    const float* x         = (const float*)d_in[0];
    const float* w_cq      = (const float*)d_in[1];
    const float* g_qnorm   = (const float*)d_in[2];
    const float* w_dq_nope = (const float*)d_in[3];
    const float* w_dq_rope = (const float*)d_in[4];
    const float* w_ckv     = (const float*)d_in[5];
    const float* g_kvnorm  = (const float*)d_in[6];
    const float* w_dk_nope = (const float*)d_in[7];
    const float* w_dv      = (const float*)d_in[8];
    const float* w_krope   = (const float*)d_in[9];
    const float* w_imp     = (const float*)d_in[10];
    const float* w_selk    = (const float*)d_in[11];
    const float* w_selv    = (const float*)d_in[12];
    const float* w_wink    = (const float*)d_in[13];
    const float* w_winv    = (const float*)d_in[14];
    const float* w_gate    = (const float*)d_in[15];
    const float* w_proj    = (const float*)d_in[16];
    float* out = (float*)d_out;

    float* base = nullptr;
    cudaGetSymbolAddress((void**)&base, g_scratch);

    float* wc1    = base + OFF_WC1;
    float* wtf    = base + OFF_WTF;
    float* xtf    = base + OFF_XTF;
    float* f0     = base + OFF_F0;
    float* qout   = base + OFF_QOUT;
    float* kvout  = base + OFF_KVOUT;
    float* winout = base + OFF_WINOUT;
    float* selkv  = base + OFF_SELKV;
    float* xmean  = base + OFF_XMEAN;
    float* gate   = base + OFF_GATE;
    float* scores = base + OFF_SCORES;
    int*   idx    = (int*)(base + OFF_IDX);
    float* Qb     = base + OFF_Q;
    float* K1b    = base + OFF_K1;
    float* KWb    = base + OFF_KW;
    float* KSb    = base + OFF_KS;
    float* att0   = base + OFF_ATTN;
    float* att1   = base + OFF_ATTN2;
    float* att2   = base + OFF_ATTN3;

    const int M = BB * TT;  // 2048

    cudaFuncSetAttribute(gemm_multi, cudaFuncAttributeMaxDynamicSharedMemorySize, G2_SMEM);
    cudaFuncSetAttribute(attn_mma, cudaFuncAttributeMaxDynamicSharedMemorySize, ATTN_SMEM);

    // 1) prep
    prep_kernel<<<3080 + WTF_BLOCKS, 256>>>(x, w_imp, scores, xtf, xmean,
                                            w_cq, w_ckv, w_krope, wc1,
                                            w_wink, w_winv, w_selk, w_selv, w_proj,
                                            w_dq_nope, w_dq_rope, w_dk_nope, w_dv, wtf);

    // 2) topk + gate
    topk_gate_kernel<<<4, 1024>>>(scores, idx, xmean, w_gate, gate);

    // 3) mega GEMM 1: winout | f0 | selkv
    {
        GemmJobs jobs;
        jobs.j[0] = {xtf, CC, wtf + WTF_WINK, 1536, 1536, wtf + WTF_WINV, 512,
                     winout, 2048, CC, 0, 16, nullptr, 1};
        jobs.j[1] = {xtf, CC, wc1, 256, 256, wc1, 256,
                     f0, 256, CC, 256, 2, nullptr, 1};
        jobs.j[2] = {xtf, CC, wtf + WTF_SELK, 1536, 1536, wtf + WTF_SELV, 512,
                     selkv, 2048, CC, 288, 16, idx, 1};
        gemm_multi<<<352, 256, G2_SMEM>>>(jobs, 3);
    }

    // 4) rms on f0
    rms2_kernel<<<M, 128>>>(f0, g_qnorm, g_kvnorm);

    // 5) mega GEMM 2: qout | kvout
    {
        GemmJobs jobs;
        jobs.j[0] = {f0, 256, wtf + WTF_DQN, 512, 512, wtf + WTF_DQR, 1024,
                     qout, 1536, 96, 0, 12, nullptr, 1};
        jobs.j[1] = {f0 + 96, 256, wtf + WTF_DKN, 512, 512, wtf + WTF_DV, 512,
                     kvout, 1024, 32, 192, 8, nullptr, 1};
        jobs.j[2] = jobs.j[1];
        gemm_multi<<<320, 256, G2_SMEM>>>(jobs, 2);
    }

    // 6) assembles
    assemble_all_kernel<<<6656, 512>>>(qout, kvout, f0, selkv, winout,
                                       Qb, K1b, KSb, KWb);

    // 7) attention
    attn_mma<<<dim3(24, HH, BB), 256, ATTN_SMEM>>>(Qb, K1b, KSb, KWb,
                                                   kvout, selkv, winout,
                                                   gate, att0, att1, att2);

    // 7b) att0 = round(att0+att1+att2)
    attadd3_kernel<<<(M * HH * VD) / 1024, 256>>>(att0, att1, att2);

    // 8) output projection: single job, K=512, writes out directly
    {
        GemmJobs jobs;
        jobs.j[0] = {att0, HH * VD, wtf + WTF_PROJ, CC, CC, wtf + WTF_PROJ, CC,
                     out, CC, 512, 0, 8, nullptr, 0};
        jobs.j[1] = jobs.j[0];
        jobs.j[2] = jobs.j[0];
        gemm_multi<<<128, 256, G2_SMEM>>>(jobs, 1);
    }
}